// round 4
// baseline (speedup 1.0000x reference)
#include <cuda_runtime.h>
#include <math.h>

#define BATCH  4096
#define HIDDEN 1024
#define INPUT  512
#define NOUT   (4 * HIDDEN)   // 4096

#define BM 128
#define BN 128
#define BK 16
#define LDT 132               // padded smem row stride (floats)

// 64 MB scratch for lin = x@Wih^T + h@Whh^T  (static __device__ — allowed)
__device__ float g_lin[(size_t)BATCH * NOUT];

// ---------------- packed f32x2 helpers ----------------
__device__ __forceinline__ unsigned long long pack2(float lo, float hi) {
    unsigned long long r;
    asm("mov.b64 %0, {%1, %2};" : "=l"(r) : "f"(lo), "f"(hi));
    return r;
}
__device__ __forceinline__ void unpack2(unsigned long long v, float& lo, float& hi) {
    asm("mov.b64 {%0, %1}, %2;" : "=f"(lo), "=f"(hi) : "l"(v));
}
__device__ __forceinline__ void fma2(unsigned long long& c,
                                     unsigned long long a,
                                     unsigned long long b) {
    asm("fma.rn.f32x2 %0, %1, %2, %0;" : "+l"(c) : "l"(a), "l"(b));
}

// ---------------- GEMM: lin = X * Wih^T + H * Whh^T ----------------
// A (activations) row-major [M,K], B (weights) row-major [N,K]  (NT layout,
// both K-contiguous). Two K-phases: K=512 (x,Wih) then K=1024 (h,Whh).
__global__ __launch_bounds__(256, 1)
void lnlstm_gemm_kernel(const float* __restrict__ x,
                        const float* __restrict__ h,
                        const float* __restrict__ wih,
                        const float* __restrict__ whh)
{
    __shared__ float As[BK][LDT];
    __shared__ float Bs[BK][LDT];

    const int tid = threadIdx.x;
    const int bm  = blockIdx.y * BM;
    const int bn  = blockIdx.x * BN;

    const int tx = tid & 15;   // n-direction (8 cols each)
    const int ty = tid >> 4;   // m-direction (8 rows each)

    // global-load mapping: idx -> (row = idx/4, k-subgroup = idx%4)
    const int r0 = tid >> 2;           // rows 0..63
    const int r1 = (tid + 256) >> 2;   // rows 64..127
    const int k4 = (tid & 3) * 4;      // k offset 0/4/8/12

    unsigned long long acc[8][4];
    #pragma unroll
    for (int i = 0; i < 8; ++i)
        #pragma unroll
        for (int j = 0; j < 4; ++j) acc[i][j] = 0ull;

    const int NT1 = INPUT / BK;              // 32 tiles in phase 1
    const int NT  = NT1 + HIDDEN / BK;       // 96 total

    float4 pa0, pa1, pb0, pb1;

    // prologue: prefetch tile 0 (phase 1: x / Wih, ld = INPUT)
    pa0 = *(const float4*)(x   + (size_t)(bm + r0) * INPUT + k4);
    pa1 = *(const float4*)(x   + (size_t)(bm + r1) * INPUT + k4);
    pb0 = *(const float4*)(wih + (size_t)(bn + r0) * INPUT + k4);
    pb1 = *(const float4*)(wih + (size_t)(bn + r1) * INPUT + k4);

    #pragma unroll 1
    for (int t = 0; t < NT; ++t) {
        __syncthreads();
        // deposit prefetched tile into smem (transposed: [k][row])
        As[k4 + 0][r0] = pa0.x; As[k4 + 1][r0] = pa0.y;
        As[k4 + 2][r0] = pa0.z; As[k4 + 3][r0] = pa0.w;
        As[k4 + 0][r1] = pa1.x; As[k4 + 1][r1] = pa1.y;
        As[k4 + 2][r1] = pa1.z; As[k4 + 3][r1] = pa1.w;
        Bs[k4 + 0][r0] = pb0.x; Bs[k4 + 1][r0] = pb0.y;
        Bs[k4 + 2][r0] = pb0.z; Bs[k4 + 3][r0] = pb0.w;
        Bs[k4 + 0][r1] = pb1.x; Bs[k4 + 1][r1] = pb1.y;
        Bs[k4 + 2][r1] = pb1.z; Bs[k4 + 3][r1] = pb1.w;
        __syncthreads();

        // prefetch next tile while computing this one
        if (t + 1 < NT) {
            const int tn = t + 1;
            const float* gA;
            const float* gB;
            int ld, k0;
            if (tn < NT1) { gA = x; gB = wih; ld = INPUT;  k0 = tn * BK; }
            else          { gA = h; gB = whh; ld = HIDDEN; k0 = (tn - NT1) * BK; }
            pa0 = *(const float4*)(gA + (size_t)(bm + r0) * ld + k0 + k4);
            pa1 = *(const float4*)(gA + (size_t)(bm + r1) * ld + k0 + k4);
            pb0 = *(const float4*)(gB + (size_t)(bn + r0) * ld + k0 + k4);
            pb1 = *(const float4*)(gB + (size_t)(bn + r1) * ld + k0 + k4);
        }

        #pragma unroll
        for (int kk = 0; kk < BK; ++kk) {
            const float4 a0 = *(const float4*)&As[kk][ty * 8];
            const float4 a1 = *(const float4*)&As[kk][ty * 8 + 4];
            const float4 b0 = *(const float4*)&Bs[kk][tx * 8];
            const float4 b1 = *(const float4*)&Bs[kk][tx * 8 + 4];

            unsigned long long bb[4];
            bb[0] = pack2(b0.x, b0.y);
            bb[1] = pack2(b0.z, b0.w);
            bb[2] = pack2(b1.x, b1.y);
            bb[3] = pack2(b1.z, b1.w);

            const float av[8] = {a0.x, a0.y, a0.z, a0.w, a1.x, a1.y, a1.z, a1.w};
            #pragma unroll
            for (int i = 0; i < 8; ++i) {
                const unsigned long long aa = pack2(av[i], av[i]);
                #pragma unroll
                for (int j = 0; j < 4; ++j) fma2(acc[i][j], aa, bb[j]);
            }
        }
    }

    // write back 8x8 microtile
    float* Cp = g_lin + (size_t)(bm + ty * 8) * NOUT + bn + tx * 8;
    #pragma unroll
    for (int i = 0; i < 8; ++i) {
        float f[8];
        unpack2(acc[i][0], f[0], f[1]);
        unpack2(acc[i][1], f[2], f[3]);
        unpack2(acc[i][2], f[4], f[5]);
        unpack2(acc[i][3], f[6], f[7]);
        float4* p = (float4*)(Cp + (size_t)i * NOUT);
        p[0] = make_float4(f[0], f[1], f[2], f[3]);
        p[1] = make_float4(f[4], f[5], f[6], f[7]);
    }
}

// ---------------- block reduction (sum, sumsq) ----------------
__device__ __forceinline__ float2 block_reduce2(float a, float b, float2* sm) {
    #pragma unroll
    for (int o = 16; o > 0; o >>= 1) {
        a += __shfl_down_sync(0xffffffffu, a, o);
        b += __shfl_down_sync(0xffffffffu, b, o);
    }
    const int w = threadIdx.x >> 5;
    const int l = threadIdx.x & 31;
    if (l == 0) sm[w] = make_float2(a, b);
    __syncthreads();
    if (w == 0) {
        float2 v = (l < 8) ? sm[l] : make_float2(0.f, 0.f);
        #pragma unroll
        for (int o = 4; o > 0; o >>= 1) {
            v.x += __shfl_down_sync(0xffffffffu, v.x, o);
            v.y += __shfl_down_sync(0xffffffffu, v.y, o);
        }
        if (l == 0) sm[0] = v;
    }
    __syncthreads();
    const float2 r = sm[0];
    __syncthreads();  // protect sm before next reuse
    return r;
}

// ---------------- epilogue: chunked LN + gates + cell LN ----------------
__global__ __launch_bounds__(256, 4)
void lnlstm_epilogue_kernel(const float* __restrict__ c,
                            const float* __restrict__ lnw_h,
                            const float* __restrict__ lnb_h,
                            const float* __restrict__ lnw_c,
                            const float* __restrict__ lnb_c,
                            float* __restrict__ h_out,
                            float* __restrict__ c_out)
{
    __shared__ float2 red[8];
    const int b = blockIdx.x;
    const int t = threadIdx.x;                 // 256 threads, 4 elems each
    const float* row = g_lin + (size_t)b * NOUT;

    float gate[4][4];
    #pragma unroll
    for (int g = 0; g < 4; ++g) {
        float v[4];
        float s = 0.f, ss = 0.f;
        #pragma unroll
        for (int r = 0; r < 4; ++r) {
            v[r] = row[g * HIDDEN + t + 256 * r];
            s  += v[r];
            ss += v[r] * v[r];
        }
        const float2 tot = block_reduce2(s, ss, red);
        const float mu   = tot.x * (1.0f / HIDDEN);
        const float var  = tot.y * (1.0f / HIDDEN) - mu * mu;
        const float rstd = rsqrtf(var + 1e-5f);
        #pragma unroll
        for (int r = 0; r < 4; ++r) {
            const int j = g * HIDDEN + t + 256 * r;
            gate[g][r] = (v[r] - mu) * rstd * lnw_h[j] + lnb_h[j];
        }
    }

    float cn[4], og[4];
    float s = 0.f, ss = 0.f;
    #pragma unroll
    for (int r = 0; r < 4; ++r) {
        const int j = t + 256 * r;
        const float ig = 1.0f / (1.0f + expf(-gate[0][r]));
        const float fg = 1.0f / (1.0f + expf(-(gate[1][r] + 1.0f)));  // forget bias
        og[r]          = 1.0f / (1.0f + expf(-gate[2][r]));
        const float cc = tanhf(gate[3][r]);
        const float cv = fg * c[(size_t)b * HIDDEN + j] + ig * cc;
        cn[r] = cv;
        s  += cv;
        ss += cv * cv;
    }
    const float2 tot = block_reduce2(s, ss, red);
    const float mu   = tot.x * (1.0f / HIDDEN);
    const float var  = tot.y * (1.0f / HIDDEN) - mu * mu;
    const float rstd = rsqrtf(var + 1e-5f);
    #pragma unroll
    for (int r = 0; r < 4; ++r) {
        const int j = t + 256 * r;
        const float cln = (cn[r] - mu) * rstd * lnw_c[j] + lnb_c[j];
        h_out[(size_t)b * HIDDEN + j] = og[r] * tanhf(cln);
        c_out[(size_t)b * HIDDEN + j] = cn[r];
    }
}

// ---------------- launch ----------------
extern "C" void kernel_launch(void* const* d_in, const int* in_sizes, int n_in,
                              void* d_out, int out_size)
{
    const float* x     = (const float*)d_in[0];
    const float* h     = (const float*)d_in[1];
    const float* c     = (const float*)d_in[2];
    const float* wih   = (const float*)d_in[3];
    const float* whh   = (const float*)d_in[4];
    const float* lnw_h = (const float*)d_in[5];
    const float* lnb_h = (const float*)d_in[6];
    const float* lnw_c = (const float*)d_in[7];
    const float* lnb_c = (const float*)d_in[8];

    float* out   = (float*)d_out;
    float* h_out = out;                               // output 0: h_new
    float* c_out = out + (size_t)BATCH * HIDDEN;      // output 1: c_new

    dim3 ggrid(NOUT / BN, BATCH / BM);                // 32 x 32
    lnlstm_gemm_kernel<<<ggrid, 256>>>(x, h, wih, whh);

    lnlstm_epilogue_kernel<<<BATCH, 256>>>(c, lnw_h, lnb_h, lnw_c, lnb_c,
                                           h_out, c_out);
}

// round 6
// speedup vs baseline: 2.2422x; 2.2422x over previous
#include <cuda_runtime.h>
#include <cuda_bf16.h>
#include <stdint.h>
#include <math.h>

#define BATCH  4096
#define HIDDEN 1024
#define INPUT  512
#define NOUT   4096
#define KTOT   1536
#define BM     128
#define BN     128
#define BK     64                 // bf16 k-elems per chunk (128 B rows)
#define NCH    (KTOT / BK)        // 24
#define STAGES 3
#define TILE_B (BM * BK * 2)      // 16384 B per tile
#define STAGE_B (4 * TILE_B)      // 65536 B (Ahi, Alo, Bhi, Blo)
#define SMEM_B (STAGES * STAGE_B) // 196608 B

// ---------------- device scratch ----------------
__device__ float         g_lin[(size_t)BATCH * NOUT];
__device__ __nv_bfloat16 g_Ahi[(size_t)BATCH * KTOT];
__device__ __nv_bfloat16 g_Alo[(size_t)BATCH * KTOT];
__device__ __nv_bfloat16 g_Bhi[(size_t)NOUT  * KTOT];
__device__ __nv_bfloat16 g_Blo[(size_t)NOUT  * KTOT];

// ---------------- helpers ----------------
__device__ __forceinline__ uint32_t smem_u32(const void* p) {
    uint32_t a;
    asm("{ .reg .u64 t; cvta.to.shared.u64 t, %1; cvt.u32.u64 %0, t; }" : "=r"(a) : "l"(p));
    return a;
}
#define CP16(dst, src) \
    asm volatile("cp.async.cg.shared.global [%0], [%1], 16;" :: "r"(dst), "l"(src) : "memory")
#define CP_COMMIT() asm volatile("cp.async.commit_group;" ::: "memory")
#define CP_WAIT(n)  asm volatile("cp.async.wait_group %0;" :: "n"(n) : "memory")

__device__ __forceinline__ void ldsm4(uint32_t* r, uint32_t addr) {
    asm volatile("ldmatrix.sync.aligned.m8n8.x4.shared.b16 {%0,%1,%2,%3}, [%4];"
                 : "=r"(r[0]), "=r"(r[1]), "=r"(r[2]), "=r"(r[3]) : "r"(addr));
}
__device__ __forceinline__ void mma16816(float* d, const uint32_t* a,
                                         uint32_t b0, uint32_t b1) {
    asm volatile("mma.sync.aligned.m16n8k16.row.col.f32.bf16.bf16.f32 "
                 "{%0,%1,%2,%3}, {%4,%5,%6,%7}, {%8,%9}, {%0,%1,%2,%3};"
                 : "+f"(d[0]), "+f"(d[1]), "+f"(d[2]), "+f"(d[3])
                 : "r"(a[0]), "r"(a[1]), "r"(a[2]), "r"(a[3]), "r"(b0), "r"(b1));
}
// tile-local smem address with XOR-8 swizzle (128 B rows, 16 B chunks)
__device__ __forceinline__ uint32_t saddr(uint32_t tile, int row, int c) {
    return tile + (uint32_t)(row * 128) + ((uint32_t)((c ^ (row & 7)) << 4));
}

// ---------------- split-bf16 conversion ----------------
__global__ __launch_bounds__(256)
void lnlstm_convert(const float* __restrict__ x,  const float* __restrict__ h,
                    const float* __restrict__ wi, const float* __restrict__ wh)
{
    const uint32_t idx = blockIdx.x * 256u + threadIdx.x;
    const uint32_t e0  = idx * 4u;
    const int row = e0 / KTOT;
    const int col = e0 % KTOT;
    const float* s1 = blockIdx.y ? wi : x;
    const float* s2 = blockIdx.y ? wh : h;
    float4 v;
    if (col < INPUT) v = *(const float4*)(s1 + (size_t)row * INPUT  + col);
    else             v = *(const float4*)(s2 + (size_t)row * HIDDEN + (col - INPUT));
    __nv_bfloat16* hi = blockIdx.y ? g_Bhi : g_Ahi;
    __nv_bfloat16* lo = blockIdx.y ? g_Blo : g_Alo;
    const __nv_bfloat16 h0 = __float2bfloat16(v.x), h1 = __float2bfloat16(v.y);
    const __nv_bfloat16 h2 = __float2bfloat16(v.z), h3 = __float2bfloat16(v.w);
    __nv_bfloat162 hp0; hp0.x = h0; hp0.y = h1;
    __nv_bfloat162 hp1; hp1.x = h2; hp1.y = h3;
    __nv_bfloat162 lp0; lp0.x = __float2bfloat16(v.x - __bfloat162float(h0));
    lp0.y = __float2bfloat16(v.y - __bfloat162float(h1));
    __nv_bfloat162 lp1; lp1.x = __float2bfloat16(v.z - __bfloat162float(h2));
    lp1.y = __float2bfloat16(v.w - __bfloat162float(h3));
    *(__nv_bfloat162*)(hi + e0)     = hp0;
    *(__nv_bfloat162*)(hi + e0 + 2) = hp1;
    *(__nv_bfloat162*)(lo + e0)     = lp0;
    *(__nv_bfloat162*)(lo + e0 + 2) = lp1;
}

// ---------------- GEMM: g_lin = A * B^T (split-bf16, fp32 accum, mma.sync) ----------------
__global__ void __launch_bounds__(256, 1)
lnlstm_mma_gemm()
{
    extern __shared__ char smem[];
    const uint32_t sb = smem_u32(smem);
    const int tid  = threadIdx.x;
    const int wid  = tid >> 5;
    const int lane = tid & 31;
    const int m0 = blockIdx.y * BM;
    const int n0 = blockIdx.x * BN;

    // ---- cp.async mapping: thread -> (row, 4 consecutive 16B chunks) ----
    const int trow = tid >> 1;            // 0..127
    const int tc0  = (tid & 1) * 4;       // 0 or 4
    const __nv_bfloat16* gAh = g_Ahi + (size_t)(m0 + trow) * KTOT + tc0 * 8;
    const __nv_bfloat16* gAl = g_Alo + (size_t)(m0 + trow) * KTOT + tc0 * 8;
    const __nv_bfloat16* gBh = g_Bhi + (size_t)(n0 + trow) * KTOT + tc0 * 8;
    const __nv_bfloat16* gBl = g_Blo + (size_t)(n0 + trow) * KTOT + tc0 * 8;
    uint32_t dofs[4];
    #pragma unroll
    for (int c = 0; c < 4; ++c)
        dofs[c] = (uint32_t)(trow * 128) + ((uint32_t)(((tc0 + c) ^ (trow & 7)) << 4));

    // ---- ldmatrix per-lane bases ----
    const int sub = lane >> 3, r8 = lane & 7;
    const int rA  = (wid >> 2) * 64 + (sub & 1) * 8 + r8;   // + mi*16
    const int cA  = sub >> 1;                               // + ks*2
    const int rB  = (wid & 3) * 32 + (sub >> 1) * 8 + r8;   // + ng*16
    const int cB  = sub & 1;                                // + ks*2

    float acc[4][4][4];
    #pragma unroll
    for (int i = 0; i < 4; ++i)
        #pragma unroll
        for (int j = 0; j < 4; ++j)
            #pragma unroll
            for (int q = 0; q < 4; ++q) acc[i][j][q] = 0.f;

    // ---- stage loader ----
    auto load_stage = [&](int ch, int s) {
        const uint32_t base = sb + (uint32_t)s * STAGE_B;
        const size_t ke = (size_t)ch * BK;   // element offset
        #pragma unroll
        for (int c = 0; c < 4; ++c) {
            CP16(base + dofs[c],               gAh + ke + c * 8);
            CP16(base + TILE_B + dofs[c],      gAl + ke + c * 8);
            CP16(base + 2 * TILE_B + dofs[c],  gBh + ke + c * 8);
            CP16(base + 3 * TILE_B + dofs[c],  gBl + ke + c * 8);
        }
    };

    // prologue: fill STAGES-1 stages
    load_stage(0, 0); CP_COMMIT();
    load_stage(1, 1); CP_COMMIT();

    #pragma unroll 1
    for (int ch = 0; ch < NCH; ++ch) {
        CP_WAIT(1);
        __syncthreads();
        // issue next stage into the buffer consumed (STAGES-1) iters ago
        if (ch + STAGES - 1 < NCH)
            load_stage(ch + STAGES - 1, (ch + STAGES - 1) % STAGES);
        CP_COMMIT();

        const uint32_t stb = sb + (uint32_t)(ch % STAGES) * STAGE_B;
        const uint32_t tAh = stb, tAl = stb + TILE_B;
        const uint32_t tBh = stb + 2 * TILE_B, tBl = stb + 3 * TILE_B;

        #pragma unroll
        for (int ks = 0; ks < 4; ++ks) {
            uint32_t ah[4][4], al[4][4], bh[2][4], bl[2][4];
            #pragma unroll
            for (int mi = 0; mi < 4; ++mi) {
                const int row = rA + mi * 16, c = ks * 2 + cA;
                ldsm4(ah[mi], saddr(tAh, row, c));
                ldsm4(al[mi], saddr(tAl, row, c));
            }
            #pragma unroll
            for (int ng = 0; ng < 2; ++ng) {
                const int row = rB + ng * 16, c = ks * 2 + cB;
                ldsm4(bh[ng], saddr(tBh, row, c));
                ldsm4(bl[ng], saddr(tBl, row, c));
            }
            #pragma unroll
            for (int mi = 0; mi < 4; ++mi) {
                #pragma unroll
                for (int ni = 0; ni < 4; ++ni) {
                    const int g = ni >> 1, o = (ni & 1) * 2;
                    mma16816(acc[mi][ni], ah[mi], bh[g][o], bh[g][o + 1]);  // hi*hi
                    mma16816(acc[mi][ni], ah[mi], bl[g][o], bl[g][o + 1]);  // hi*lo
                    mma16816(acc[mi][ni], al[mi], bh[g][o], bh[g][o + 1]);  // lo*hi
                }
            }
        }
    }

    // ---- write back ----
    const int g = lane >> 2, tq = lane & 3;
    #pragma unroll
    for (int mi = 0; mi < 4; ++mi) {
        const int row = m0 + (wid >> 2) * 64 + mi * 16 + g;
        #pragma unroll
        for (int ni = 0; ni < 4; ++ni) {
            const int col = n0 + (wid & 3) * 32 + ni * 8 + tq * 2;
            float* p = g_lin + (size_t)row * NOUT + col;
            *(float2*)p                       = make_float2(acc[mi][ni][0], acc[mi][ni][1]);
            *(float2*)(p + (size_t)8 * NOUT)  = make_float2(acc[mi][ni][2], acc[mi][ni][3]);
        }
    }
}

// ---------------- epilogue: chunked LN + gates + cell LN ----------------
__device__ __forceinline__ float fsig(float x)  { return 1.0f / (1.0f + __expf(-x)); }
__device__ __forceinline__ float ftanh(float x) { return 1.0f - 2.0f / (1.0f + __expf(2.0f * x)); }

__global__ __launch_bounds__(256, 4)
void lnlstm_epilogue(const float* __restrict__ c,
                     const float* __restrict__ lnw_h, const float* __restrict__ lnb_h,
                     const float* __restrict__ lnw_c, const float* __restrict__ lnb_c,
                     float* __restrict__ h_out, float* __restrict__ c_out)
{
    __shared__ float4 redS[8], redQ[8];
    __shared__ float2 red2[8];
    const int b = blockIdx.x, t = threadIdx.x;
    const int w = t >> 5, l = t & 31;
    const float4* row4 = (const float4*)(g_lin + (size_t)b * NOUT);

    float4 v[4];
    float s[4], q[4];
    #pragma unroll
    for (int g = 0; g < 4; ++g) {
        v[g] = row4[g * 256 + t];
        s[g] = (v[g].x + v[g].y) + (v[g].z + v[g].w);
        q[g] = (v[g].x * v[g].x + v[g].y * v[g].y) + (v[g].z * v[g].z + v[g].w * v[g].w);
    }
    #pragma unroll
    for (int o = 16; o > 0; o >>= 1) {
        #pragma unroll
        for (int g = 0; g < 4; ++g) {
            s[g] += __shfl_down_sync(0xffffffffu, s[g], o);
            q[g] += __shfl_down_sync(0xffffffffu, q[g], o);
        }
    }
    if (l == 0) { redS[w] = make_float4(s[0], s[1], s[2], s[3]);
                  redQ[w] = make_float4(q[0], q[1], q[2], q[3]); }
    __syncthreads();
    if (w == 0) {
        float4 S = (l < 8) ? redS[l] : make_float4(0, 0, 0, 0);
        float4 Q = (l < 8) ? redQ[l] : make_float4(0, 0, 0, 0);
        #pragma unroll
        for (int o = 4; o > 0; o >>= 1) {
            S.x += __shfl_down_sync(0xffffffffu, S.x, o); S.y += __shfl_down_sync(0xffffffffu, S.y, o);
            S.z += __shfl_down_sync(0xffffffffu, S.z, o); S.w += __shfl_down_sync(0xffffffffu, S.w, o);
            Q.x += __shfl_down_sync(0xffffffffu, Q.x, o); Q.y += __shfl_down_sync(0xffffffffu, Q.y, o);
            Q.z += __shfl_down_sync(0xffffffffu, Q.z, o); Q.w += __shfl_down_sync(0xffffffffu, Q.w, o);
        }
        if (l == 0) { redS[0] = S; redQ[0] = Q; }
    }
    __syncthreads();
    const float4 S = redS[0], Q = redQ[0];
    const float inv = 1.0f / HIDDEN;
    float mu[4], rs[4];
    mu[0] = S.x * inv; mu[1] = S.y * inv; mu[2] = S.z * inv; mu[3] = S.w * inv;
    rs[0] = rsqrtf(Q.x * inv - mu[0] * mu[0] + 1e-5f);
    rs[1] = rsqrtf(Q.y * inv - mu[1] * mu[1] + 1e-5f);
    rs[2] = rsqrtf(Q.z * inv - mu[2] * mu[2] + 1e-5f);
    rs[3] = rsqrtf(Q.w * inv - mu[3] * mu[3] + 1e-5f);

    #pragma unroll
    for (int g = 0; g < 4; ++g) {
        const float4 lw = ((const float4*)lnw_h)[g * 256 + t];
        const float4 lb = ((const float4*)lnb_h)[g * 256 + t];
        v[g].x = (v[g].x - mu[g]) * rs[g] * lw.x + lb.x;
        v[g].y = (v[g].y - mu[g]) * rs[g] * lw.y + lb.y;
        v[g].z = (v[g].z - mu[g]) * rs[g] * lw.z + lb.z;
        v[g].w = (v[g].w - mu[g]) * rs[g] * lw.w + lb.w;
    }

    const float4 cold = ((const float4*)c)[(size_t)b * 256 + t];
    float4 cn, og;
    cn.x = fsig(v[1].x + 1.0f) * cold.x + fsig(v[0].x) * ftanh(v[3].x);
    cn.y = fsig(v[1].y + 1.0f) * cold.y + fsig(v[0].y) * ftanh(v[3].y);
    cn.z = fsig(v[1].z + 1.0f) * cold.z + fsig(v[0].z) * ftanh(v[3].z);
    cn.w = fsig(v[1].w + 1.0f) * cold.w + fsig(v[0].w) * ftanh(v[3].w);
    og.x = fsig(v[2].x); og.y = fsig(v[2].y); og.z = fsig(v[2].z); og.w = fsig(v[2].w);

    float s2 = (cn.x + cn.y) + (cn.z + cn.w);
    float q2 = (cn.x * cn.x + cn.y * cn.y) + (cn.z * cn.z + cn.w * cn.w);
    #pragma unroll
    for (int o = 16; o > 0; o >>= 1) {
        s2 += __shfl_down_sync(0xffffffffu, s2, o);
        q2 += __shfl_down_sync(0xffffffffu, q2, o);
    }
    if (l == 0) red2[w] = make_float2(s2, q2);
    __syncthreads();
    if (w == 0) {
        float2 p = (l < 8) ? red2[l] : make_float2(0, 0);
        #pragma unroll
        for (int o = 4; o > 0; o >>= 1) {
            p.x += __shfl_down_sync(0xffffffffu, p.x, o);
            p.y += __shfl_down_sync(0xffffffffu, p.y, o);
        }
        if (l == 0) red2[0] = p;
    }
    __syncthreads();
    const float mu2 = red2[0].x * inv;
    const float rs2 = rsqrtf(red2[0].y * inv - mu2 * mu2 + 1e-5f);

    const float4 lwc = ((const float4*)lnw_c)[t];
    const float4 lbc = ((const float4*)lnb_c)[t];
    float4 ho;
    ho.x = og.x * ftanh((cn.x - mu2) * rs2 * lwc.x + lbc.x);
    ho.y = og.y * ftanh((cn.y - mu2) * rs2 * lwc.y + lbc.y);
    ho.z = og.z * ftanh((cn.z - mu2) * rs2 * lwc.z + lbc.z);
    ho.w = og.w * ftanh((cn.w - mu2) * rs2 * lwc.w + lbc.w);

    ((float4*)c_out)[(size_t)b * 256 + t] = cn;
    ((float4*)h_out)[(size_t)b * 256 + t] = ho;
}

// ---------------- launch ----------------
extern "C" void kernel_launch(void* const* d_in, const int* in_sizes, int n_in,
                              void* d_out, int out_size)
{
    const float* x     = (const float*)d_in[0];
    const float* h     = (const float*)d_in[1];
    const float* c     = (const float*)d_in[2];
    const float* wih   = (const float*)d_in[3];
    const float* whh   = (const float*)d_in[4];
    const float* lnw_h = (const float*)d_in[5];
    const float* lnb_h = (const float*)d_in[6];
    const float* lnw_c = (const float*)d_in[7];
    const float* lnb_c = (const float*)d_in[8];

    float* h_out = (float*)d_out;
    float* c_out = h_out + (size_t)BATCH * HIDDEN;

    cudaFuncSetAttribute(lnlstm_mma_gemm,
                         cudaFuncAttributeMaxDynamicSharedMemorySize, SMEM_B);

    lnlstm_convert<<<dim3((BATCH * KTOT / 4) / 256, 2), 256>>>(x, h, wih, whh);
    lnlstm_mma_gemm<<<dim3(NOUT / BN, BATCH / BM), 256, SMEM_B>>>();
    lnlstm_epilogue<<<BATCH, 256>>>(c, lnw_h, lnb_h, lnw_c, lnb_c, h_out, c_out);
}

// round 7
// speedup vs baseline: 4.6610x; 2.0787x over previous
#include <cuda_runtime.h>
#include <cuda_fp16.h>
#include <stdint.h>
#include <math.h>

#define BATCH  4096
#define HIDDEN 1024
#define INPUT  512
#define NOUT   4096
#define KTOT   1536
#define BM     128
#define BN     128
#define BK     64                 // fp16 k-elems per chunk (128 B rows)
#define NCH    (KTOT / BK)        // 24
#define STAGES 4
#define TILE_B (BM * BK * 2)      // 16384 B
#define STAGE_B (2 * TILE_B)      // 32768 B (A, B)
#define SMEM_B (STAGES * STAGE_B) // 131072 B

// ---------------- device scratch ----------------
__device__ float  g_lin[(size_t)BATCH * NOUT];
__device__ __half g_A[(size_t)BATCH * KTOT];
__device__ __half g_B[(size_t)NOUT  * KTOT];

// ---------------- helpers ----------------
__device__ __forceinline__ uint32_t smem_u32(const void* p) {
    uint32_t a;
    asm("{ .reg .u64 t; cvta.to.shared.u64 t, %1; cvt.u32.u64 %0, t; }" : "=r"(a) : "l"(p));
    return a;
}
#define CP16(dst, src) \
    asm volatile("cp.async.cg.shared.global [%0], [%1], 16;" :: "r"(dst), "l"(src) : "memory")
#define CP_COMMIT() asm volatile("cp.async.commit_group;" ::: "memory")
#define CP_WAIT(n)  asm volatile("cp.async.wait_group %0;" :: "n"(n) : "memory")

__device__ __forceinline__ void ldsm4(uint32_t* r, uint32_t addr) {
    asm volatile("ldmatrix.sync.aligned.m8n8.x4.shared.b16 {%0,%1,%2,%3}, [%4];"
                 : "=r"(r[0]), "=r"(r[1]), "=r"(r[2]), "=r"(r[3]) : "r"(addr));
}
__device__ __forceinline__ void mma16816(float* d, const uint32_t* a,
                                         uint32_t b0, uint32_t b1) {
    asm volatile("mma.sync.aligned.m16n8k16.row.col.f32.f16.f16.f32 "
                 "{%0,%1,%2,%3}, {%4,%5,%6,%7}, {%8,%9}, {%0,%1,%2,%3};"
                 : "+f"(d[0]), "+f"(d[1]), "+f"(d[2]), "+f"(d[3])
                 : "r"(a[0]), "r"(a[1]), "r"(a[2]), "r"(a[3]), "r"(b0), "r"(b1));
}
// tile-local smem address with XOR-8 swizzle (128 B rows, 16 B chunks)
__device__ __forceinline__ uint32_t saddr(uint32_t tile, int row, int c) {
    return tile + (uint32_t)(row * 128) + ((uint32_t)((c ^ (row & 7)) << 4));
}

// ---------------- fp16 conversion: A = [x|h], B = [wih|whh] ----------------
__global__ __launch_bounds__(256)
void lnlstm_convert(const float* __restrict__ x,  const float* __restrict__ h,
                    const float* __restrict__ wi, const float* __restrict__ wh)
{
    const uint32_t idx = blockIdx.x * 256u + threadIdx.x;
    const uint32_t e0  = idx * 4u;
    const int row = e0 / KTOT;
    const int col = e0 % KTOT;
    const float* s1 = blockIdx.y ? wi : x;
    const float* s2 = blockIdx.y ? wh : h;
    float4 v;
    if (col < INPUT) v = *(const float4*)(s1 + (size_t)row * INPUT  + col);
    else             v = *(const float4*)(s2 + (size_t)row * HIDDEN + (col - INPUT));
    __half* dst = blockIdx.y ? g_B : g_A;
    __half2 p0 = __floats2half2_rn(v.x, v.y);
    __half2 p1 = __floats2half2_rn(v.z, v.w);
    *(__half2*)(dst + e0)     = p0;
    *(__half2*)(dst + e0 + 2) = p1;
}

// ---------------- GEMM: g_lin = A * B^T (fp16 mma.sync, fp32 accum) ----------------
__global__ void __launch_bounds__(256, 1)
lnlstm_mma_gemm()
{
    extern __shared__ char smem[];
    const uint32_t sb = smem_u32(smem);
    const int tid  = threadIdx.x;
    const int wid  = tid >> 5;
    const int lane = tid & 31;
    const int m0 = blockIdx.y * BM;
    const int n0 = blockIdx.x * BN;

    // cp.async mapping: thread -> (row, 4 consecutive 16B chunks)
    const int trow = tid >> 1;            // 0..127
    const int tc0  = (tid & 1) * 4;       // 0 or 4
    const __half* gA = g_A + (size_t)(m0 + trow) * KTOT + tc0 * 8;
    const __half* gB = g_B + (size_t)(n0 + trow) * KTOT + tc0 * 8;
    uint32_t dofs[4];
    #pragma unroll
    for (int c = 0; c < 4; ++c)
        dofs[c] = (uint32_t)(trow * 128) + ((uint32_t)(((tc0 + c) ^ (trow & 7)) << 4));

    // ldmatrix per-lane bases
    const int sub = lane >> 3, r8 = lane & 7;
    const int rA  = (wid >> 2) * 64 + (sub & 1) * 8 + r8;   // + mi*16
    const int cA  = sub >> 1;                               // + ks*2
    const int rB  = (wid & 3) * 32 + (sub >> 1) * 8 + r8;   // + ng*16
    const int cB  = sub & 1;                                // + ks*2

    float acc[4][4][4];
    #pragma unroll
    for (int i = 0; i < 4; ++i)
        #pragma unroll
        for (int j = 0; j < 4; ++j)
            #pragma unroll
            for (int q = 0; q < 4; ++q) acc[i][j][q] = 0.f;

    auto load_stage = [&](int ch, int s) {
        const uint32_t base = sb + (uint32_t)s * STAGE_B;
        const size_t ke = (size_t)ch * BK;
        #pragma unroll
        for (int c = 0; c < 4; ++c) {
            CP16(base + dofs[c],          gA + ke + c * 8);
            CP16(base + TILE_B + dofs[c], gB + ke + c * 8);
        }
    };

    // prologue: fill STAGES-1 stages
    load_stage(0, 0); CP_COMMIT();
    load_stage(1, 1); CP_COMMIT();
    load_stage(2, 2); CP_COMMIT();

    #pragma unroll 1
    for (int ch = 0; ch < NCH; ++ch) {
        CP_WAIT(2);
        __syncthreads();
        if (ch + STAGES - 1 < NCH)
            load_stage(ch + STAGES - 1, (ch + STAGES - 1) % STAGES);
        CP_COMMIT();

        const uint32_t stb = sb + (uint32_t)(ch % STAGES) * STAGE_B;
        const uint32_t tA = stb, tB = stb + TILE_B;

        #pragma unroll
        for (int ks = 0; ks < 4; ++ks) {
            uint32_t a[4][4], b[2][4];
            #pragma unroll
            for (int mi = 0; mi < 4; ++mi)
                ldsm4(a[mi], saddr(tA, rA + mi * 16, ks * 2 + cA));
            #pragma unroll
            for (int ng = 0; ng < 2; ++ng)
                ldsm4(b[ng], saddr(tB, rB + ng * 16, ks * 2 + cB));
            #pragma unroll
            for (int mi = 0; mi < 4; ++mi) {
                #pragma unroll
                for (int ni = 0; ni < 4; ++ni) {
                    const int g = ni >> 1, o = (ni & 1) * 2;
                    mma16816(acc[mi][ni], a[mi], b[g][o], b[g][o + 1]);
                }
            }
        }
    }

    // writeback
    const int g = lane >> 2, tq = lane & 3;
    #pragma unroll
    for (int mi = 0; mi < 4; ++mi) {
        const int row = m0 + (wid >> 2) * 64 + mi * 16 + g;
        #pragma unroll
        for (int ni = 0; ni < 4; ++ni) {
            const int col = n0 + (wid & 3) * 32 + ni * 8 + tq * 2;
            float* p = g_lin + (size_t)row * NOUT + col;
            *(float2*)p                      = make_float2(acc[mi][ni][0], acc[mi][ni][1]);
            *(float2*)(p + (size_t)8 * NOUT) = make_float2(acc[mi][ni][2], acc[mi][ni][3]);
        }
    }
}

// ---------------- epilogue: chunked LN + gates + cell LN ----------------
__device__ __forceinline__ float fsig(float x)  { return 1.0f / (1.0f + __expf(-x)); }
__device__ __forceinline__ float ftanh(float x) { return 1.0f - 2.0f / (1.0f + __expf(2.0f * x)); }

__global__ __launch_bounds__(256, 4)
void lnlstm_epilogue(const float* __restrict__ c,
                     const float* __restrict__ lnw_h, const float* __restrict__ lnb_h,
                     const float* __restrict__ lnw_c, const float* __restrict__ lnb_c,
                     float* __restrict__ h_out, float* __restrict__ c_out)
{
    __shared__ float4 redS[8], redQ[8];
    __shared__ float2 red2[8];
    const int b = blockIdx.x, t = threadIdx.x;
    const int w = t >> 5, l = t & 31;
    const float4* row4 = (const float4*)(g_lin + (size_t)b * NOUT);

    float4 v[4];
    float s[4], q[4];
    #pragma unroll
    for (int g = 0; g < 4; ++g) {
        v[g] = row4[g * 256 + t];
        s[g] = (v[g].x + v[g].y) + (v[g].z + v[g].w);
        q[g] = (v[g].x * v[g].x + v[g].y * v[g].y) + (v[g].z * v[g].z + v[g].w * v[g].w);
    }
    #pragma unroll
    for (int o = 16; o > 0; o >>= 1) {
        #pragma unroll
        for (int g = 0; g < 4; ++g) {
            s[g] += __shfl_down_sync(0xffffffffu, s[g], o);
            q[g] += __shfl_down_sync(0xffffffffu, q[g], o);
        }
    }
    if (l == 0) { redS[w] = make_float4(s[0], s[1], s[2], s[3]);
                  redQ[w] = make_float4(q[0], q[1], q[2], q[3]); }
    __syncthreads();
    if (w == 0) {
        float4 S = (l < 8) ? redS[l] : make_float4(0, 0, 0, 0);
        float4 Q = (l < 8) ? redQ[l] : make_float4(0, 0, 0, 0);
        #pragma unroll
        for (int o = 4; o > 0; o >>= 1) {
            S.x += __shfl_down_sync(0xffffffffu, S.x, o); S.y += __shfl_down_sync(0xffffffffu, S.y, o);
            S.z += __shfl_down_sync(0xffffffffu, S.z, o); S.w += __shfl_down_sync(0xffffffffu, S.w, o);
            Q.x += __shfl_down_sync(0xffffffffu, Q.x, o); Q.y += __shfl_down_sync(0xffffffffu, Q.y, o);
            Q.z += __shfl_down_sync(0xffffffffu, Q.z, o); Q.w += __shfl_down_sync(0xffffffffu, Q.w, o);
        }
        if (l == 0) { redS[0] = S; redQ[0] = Q; }
    }
    __syncthreads();
    const float4 S = redS[0], Q = redQ[0];
    const float inv = 1.0f / HIDDEN;
    float mu[4], rs[4];
    mu[0] = S.x * inv; mu[1] = S.y * inv; mu[2] = S.z * inv; mu[3] = S.w * inv;
    rs[0] = rsqrtf(Q.x * inv - mu[0] * mu[0] + 1e-5f);
    rs[1] = rsqrtf(Q.y * inv - mu[1] * mu[1] + 1e-5f);
    rs[2] = rsqrtf(Q.z * inv - mu[2] * mu[2] + 1e-5f);
    rs[3] = rsqrtf(Q.w * inv - mu[3] * mu[3] + 1e-5f);

    #pragma unroll
    for (int g = 0; g < 4; ++g) {
        const float4 lw = ((const float4*)lnw_h)[g * 256 + t];
        const float4 lb = ((const float4*)lnb_h)[g * 256 + t];
        v[g].x = (v[g].x - mu[g]) * rs[g] * lw.x + lb.x;
        v[g].y = (v[g].y - mu[g]) * rs[g] * lw.y + lb.y;
        v[g].z = (v[g].z - mu[g]) * rs[g] * lw.z + lb.z;
        v[g].w = (v[g].w - mu[g]) * rs[g] * lw.w + lb.w;
    }

    const float4 cold = ((const float4*)c)[(size_t)b * 256 + t];
    float4 cn, og;
    cn.x = fsig(v[1].x + 1.0f) * cold.x + fsig(v[0].x) * ftanh(v[3].x);
    cn.y = fsig(v[1].y + 1.0f) * cold.y + fsig(v[0].y) * ftanh(v[3].y);
    cn.z = fsig(v[1].z + 1.0f) * cold.z + fsig(v[0].z) * ftanh(v[3].z);
    cn.w = fsig(v[1].w + 1.0f) * cold.w + fsig(v[0].w) * ftanh(v[3].w);
    og.x = fsig(v[2].x); og.y = fsig(v[2].y); og.z = fsig(v[2].z); og.w = fsig(v[2].w);

    float s2 = (cn.x + cn.y) + (cn.z + cn.w);
    float q2 = (cn.x * cn.x + cn.y * cn.y) + (cn.z * cn.z + cn.w * cn.w);
    #pragma unroll
    for (int o = 16; o > 0; o >>= 1) {
        s2 += __shfl_down_sync(0xffffffffu, s2, o);
        q2 += __shfl_down_sync(0xffffffffu, q2, o);
    }
    if (l == 0) red2[w] = make_float2(s2, q2);
    __syncthreads();
    if (w == 0) {
        float2 p = (l < 8) ? red2[l] : make_float2(0, 0);
        #pragma unroll
        for (int o = 4; o > 0; o >>= 1) {
            p.x += __shfl_down_sync(0xffffffffu, p.x, o);
            p.y += __shfl_down_sync(0xffffffffu, p.y, o);
        }
        if (l == 0) red2[0] = p;
    }
    __syncthreads();
    const float mu2 = red2[0].x * inv;
    const float rs2 = rsqrtf(red2[0].y * inv - mu2 * mu2 + 1e-5f);

    const float4 lwc = ((const float4*)lnw_c)[t];
    const float4 lbc = ((const float4*)lnb_c)[t];
    float4 ho;
    ho.x = og.x * ftanh((cn.x - mu2) * rs2 * lwc.x + lbc.x);
    ho.y = og.y * ftanh((cn.y - mu2) * rs2 * lwc.y + lbc.y);
    ho.z = og.z * ftanh((cn.z - mu2) * rs2 * lwc.z + lbc.z);
    ho.w = og.w * ftanh((cn.w - mu2) * rs2 * lwc.w + lbc.w);

    ((float4*)c_out)[(size_t)b * 256 + t] = cn;
    ((float4*)h_out)[(size_t)b * 256 + t] = ho;
}

// ---------------- launch ----------------
extern "C" void kernel_launch(void* const* d_in, const int* in_sizes, int n_in,
                              void* d_out, int out_size)
{
    const float* x     = (const float*)d_in[0];
    const float* h     = (const float*)d_in[1];
    const float* c     = (const float*)d_in[2];
    const float* wih   = (const float*)d_in[3];
    const float* whh   = (const float*)d_in[4];
    const float* lnw_h = (const float*)d_in[5];
    const float* lnb_h = (const float*)d_in[6];
    const float* lnw_c = (const float*)d_in[7];
    const float* lnb_c = (const float*)d_in[8];

    float* h_out = (float*)d_out;
    float* c_out = h_out + (size_t)BATCH * HIDDEN;

    cudaFuncSetAttribute(lnlstm_mma_gemm,
                         cudaFuncAttributeMaxDynamicSharedMemorySize, SMEM_B);

    lnlstm_convert<<<dim3((BATCH * KTOT / 4) / 256, 2), 256>>>(x, h, wih, whh);
    lnlstm_mma_gemm<<<dim3(NOUT / BN, BATCH / BM), 256, SMEM_B>>>();
    lnlstm_epilogue<<<BATCH, 256>>>(c, lnw_h, lnb_h, lnw_c, lnb_c, h_out, c_out);
}

// round 8
// speedup vs baseline: 4.7305x; 1.0149x over previous
#include <cuda_runtime.h>
#include <cuda_fp16.h>
#include <stdint.h>
#include <math.h>

#define BATCH  4096
#define HIDDEN 1024
#define INPUT  512
#define NOUT   4096
#define KTOT   1536
#define BM     128
#define BN     256
#define BK     64
#define NCH    (KTOT / BK)          // 24
#define STAGES 4
#define TILEA_B (BM * BK * 2)       // 16384 B
#define TILEB_B (BN * BK * 2)       // 32768 B
#define STAGE_B (TILEA_B + TILEB_B) // 49152 B
#define SMEM_B  (STAGES * STAGE_B)  // 196608 B

// ---------------- device scratch ----------------
__device__ __half g_lin[(size_t)BATCH * NOUT];   // fp16 lin scratch (32 MB)
__device__ __half g_A[(size_t)BATCH * KTOT];
__device__ __half g_B[(size_t)NOUT  * KTOT];

// ---------------- helpers ----------------
__device__ __forceinline__ uint32_t smem_u32(const void* p) {
    uint32_t a;
    asm("{ .reg .u64 t; cvta.to.shared.u64 t, %1; cvt.u32.u64 %0, t; }" : "=r"(a) : "l"(p));
    return a;
}
#define CP16(dst, src) \
    asm volatile("cp.async.cg.shared.global [%0], [%1], 16;" :: "r"(dst), "l"(src) : "memory")
#define CP_COMMIT() asm volatile("cp.async.commit_group;" ::: "memory")
#define CP_WAIT(n)  asm volatile("cp.async.wait_group %0;" :: "n"(n) : "memory")

__device__ __forceinline__ void ldsm4(uint32_t* r, uint32_t addr) {
    asm volatile("ldmatrix.sync.aligned.m8n8.x4.shared.b16 {%0,%1,%2,%3}, [%4];"
                 : "=r"(r[0]), "=r"(r[1]), "=r"(r[2]), "=r"(r[3]) : "r"(addr));
}
__device__ __forceinline__ void mma16816(float* d, const uint32_t* a,
                                         uint32_t b0, uint32_t b1) {
    asm volatile("mma.sync.aligned.m16n8k16.row.col.f32.f16.f16.f32 "
                 "{%0,%1,%2,%3}, {%4,%5,%6,%7}, {%8,%9}, {%0,%1,%2,%3};"
                 : "+f"(d[0]), "+f"(d[1]), "+f"(d[2]), "+f"(d[3])
                 : "r"(a[0]), "r"(a[1]), "r"(a[2]), "r"(a[3]), "r"(b0), "r"(b1));
}
// tile-local smem address with XOR-8 swizzle (128 B rows, 16 B chunks)
__device__ __forceinline__ uint32_t saddr(uint32_t tile, int row, int c) {
    return tile + (uint32_t)(row * 128) + ((uint32_t)((c ^ (row & 7)) << 4));
}

// ---------------- fp16 conversion: A = [x|h], B = [wih|whh] ----------------
__global__ __launch_bounds__(256)
void lnlstm_convert(const float* __restrict__ x,  const float* __restrict__ h,
                    const float* __restrict__ wi, const float* __restrict__ wh)
{
    const uint32_t idx = blockIdx.x * 256u + threadIdx.x;
    const uint32_t e0  = idx * 4u;
    const int row = e0 / KTOT;
    const int col = e0 % KTOT;
    const float* s1 = blockIdx.y ? wi : x;
    const float* s2 = blockIdx.y ? wh : h;
    float4 v;
    if (col < INPUT) v = *(const float4*)(s1 + (size_t)row * INPUT  + col);
    else             v = *(const float4*)(s2 + (size_t)row * HIDDEN + (col - INPUT));
    __half* dst = blockIdx.y ? g_B : g_A;
    *(__half2*)(dst + e0)     = __floats2half2_rn(v.x, v.y);
    *(__half2*)(dst + e0 + 2) = __floats2half2_rn(v.z, v.w);
}

// ---------------- GEMM: g_lin = A * B^T (fp16 mma.sync, fp32 accum) ----------------
// CTA 128x256, 8 warps as 2(M) x 4(N), warp tile 64x64.
__global__ void __launch_bounds__(256, 1)
lnlstm_mma_gemm()
{
    extern __shared__ char smem[];
    const uint32_t sb = smem_u32(smem);
    const int tid  = threadIdx.x;
    const int wid  = tid >> 5;
    const int lane = tid & 31;
    const int m0 = blockIdx.y * BM;
    const int n0 = blockIdx.x * BN;

    // cp.async mapping
    const int trow = tid >> 1;            // 0..127
    const int tc0  = (tid & 1) * 4;       // 0 or 4
    const __half* gA  = g_A + (size_t)(m0 + trow) * KTOT + tc0 * 8;
    const __half* gB0 = g_B + (size_t)(n0 + trow) * KTOT + tc0 * 8;
    const __half* gB1 = g_B + (size_t)(n0 + trow + 128) * KTOT + tc0 * 8;
    uint32_t dofs[4];
    #pragma unroll
    for (int c = 0; c < 4; ++c)
        dofs[c] = (uint32_t)(trow * 128) + ((uint32_t)(((tc0 + c) ^ (trow & 7)) << 4));

    // ldmatrix per-lane bases
    const int sub = lane >> 3, r8 = lane & 7;
    const int rA  = (wid >> 2) * 64 + (sub & 1) * 8 + r8;   // + mi*16
    const int cA  = sub >> 1;                               // + ks*2
    const int rB  = (wid & 3) * 64 + (sub >> 1) * 8 + r8;   // + ng*16
    const int cB  = sub & 1;                                // + ks*2

    float acc[4][8][4];
    #pragma unroll
    for (int i = 0; i < 4; ++i)
        #pragma unroll
        for (int j = 0; j < 8; ++j)
            #pragma unroll
            for (int q = 0; q < 4; ++q) acc[i][j][q] = 0.f;

    auto load_stage = [&](int ch, int s) {
        const uint32_t base = sb + (uint32_t)s * STAGE_B;
        const size_t ke = (size_t)ch * BK;
        #pragma unroll
        for (int c = 0; c < 4; ++c) {
            CP16(base + dofs[c],                     gA  + ke + c * 8);
            CP16(base + TILEA_B + dofs[c],           gB0 + ke + c * 8);
            CP16(base + TILEA_B + 16384 + dofs[c],   gB1 + ke + c * 8);
        }
    };

    load_stage(0, 0); CP_COMMIT();
    load_stage(1, 1); CP_COMMIT();
    load_stage(2, 2); CP_COMMIT();

    #pragma unroll 1
    for (int ch = 0; ch < NCH; ++ch) {
        CP_WAIT(2);
        __syncthreads();
        if (ch + STAGES - 1 < NCH)
            load_stage(ch + STAGES - 1, (ch + STAGES - 1) % STAGES);
        CP_COMMIT();

        const uint32_t stb = sb + (uint32_t)(ch % STAGES) * STAGE_B;
        const uint32_t tA = stb, tB = stb + TILEA_B;

        #pragma unroll
        for (int ks = 0; ks < 4; ++ks) {
            uint32_t a[4][4], b[4][4];
            #pragma unroll
            for (int mi = 0; mi < 4; ++mi)
                ldsm4(a[mi], saddr(tA, rA + mi * 16, ks * 2 + cA));
            #pragma unroll
            for (int ng = 0; ng < 4; ++ng)
                ldsm4(b[ng], saddr(tB, rB + ng * 16, ks * 2 + cB));
            #pragma unroll
            for (int mi = 0; mi < 4; ++mi) {
                #pragma unroll
                for (int ni = 0; ni < 8; ++ni) {
                    const int g = ni >> 1, o = (ni & 1) * 2;
                    mma16816(acc[mi][ni], a[mi], b[g][o], b[g][o + 1]);
                }
            }
        }
    }

    // writeback (fp16)
    const int g = lane >> 2, tq = lane & 3;
    #pragma unroll
    for (int mi = 0; mi < 4; ++mi) {
        const int row = m0 + (wid >> 2) * 64 + mi * 16 + g;
        #pragma unroll
        for (int ni = 0; ni < 8; ++ni) {
            const int col = n0 + (wid & 3) * 64 + ni * 8 + tq * 2;
            __half* p = g_lin + (size_t)row * NOUT + col;
            *(__half2*)p                      = __floats2half2_rn(acc[mi][ni][0], acc[mi][ni][1]);
            *(__half2*)(p + (size_t)8 * NOUT) = __floats2half2_rn(acc[mi][ni][2], acc[mi][ni][3]);
        }
    }
}

// ---------------- epilogue: chunked LN + gates + cell LN ----------------
__device__ __forceinline__ float fsig(float x)  { return 1.0f / (1.0f + __expf(-x)); }
__device__ __forceinline__ float ftanh(float x) { return 1.0f - 2.0f / (1.0f + __expf(2.0f * x)); }

__global__ __launch_bounds__(256, 4)
void lnlstm_epilogue(const float* __restrict__ c,
                     const float* __restrict__ lnw_h, const float* __restrict__ lnb_h,
                     const float* __restrict__ lnw_c, const float* __restrict__ lnb_c,
                     float* __restrict__ h_out, float* __restrict__ c_out)
{
    __shared__ float4 redS[8], redQ[8];
    __shared__ float2 red2[8];
    const int b = blockIdx.x, t = threadIdx.x;
    const int w = t >> 5, l = t & 31;
    const __half2* row2 = (const __half2*)(g_lin + (size_t)b * NOUT);

    float4 v[4];
    float s[4], q[4];
    #pragma unroll
    for (int g = 0; g < 4; ++g) {
        const float2 p0 = __half22float2(row2[g * 512 + t * 2]);
        const float2 p1 = __half22float2(row2[g * 512 + t * 2 + 1]);
        v[g] = make_float4(p0.x, p0.y, p1.x, p1.y);
        s[g] = (v[g].x + v[g].y) + (v[g].z + v[g].w);
        q[g] = (v[g].x * v[g].x + v[g].y * v[g].y) + (v[g].z * v[g].z + v[g].w * v[g].w);
    }
    #pragma unroll
    for (int o = 16; o > 0; o >>= 1) {
        #pragma unroll
        for (int g = 0; g < 4; ++g) {
            s[g] += __shfl_down_sync(0xffffffffu, s[g], o);
            q[g] += __shfl_down_sync(0xffffffffu, q[g], o);
        }
    }
    if (l == 0) { redS[w] = make_float4(s[0], s[1], s[2], s[3]);
                  redQ[w] = make_float4(q[0], q[1], q[2], q[3]); }
    __syncthreads();
    if (w == 0) {
        float4 S = (l < 8) ? redS[l] : make_float4(0, 0, 0, 0);
        float4 Q = (l < 8) ? redQ[l] : make_float4(0, 0, 0, 0);
        #pragma unroll
        for (int o = 4; o > 0; o >>= 1) {
            S.x += __shfl_down_sync(0xffffffffu, S.x, o); S.y += __shfl_down_sync(0xffffffffu, S.y, o);
            S.z += __shfl_down_sync(0xffffffffu, S.z, o); S.w += __shfl_down_sync(0xffffffffu, S.w, o);
            Q.x += __shfl_down_sync(0xffffffffu, Q.x, o); Q.y += __shfl_down_sync(0xffffffffu, Q.y, o);
            Q.z += __shfl_down_sync(0xffffffffu, Q.z, o); Q.w += __shfl_down_sync(0xffffffffu, Q.w, o);
        }
        if (l == 0) { redS[0] = S; redQ[0] = Q; }
    }
    __syncthreads();
    const float4 S = redS[0], Q = redQ[0];
    const float inv = 1.0f / HIDDEN;
    float mu[4], rs[4];
    mu[0] = S.x * inv; mu[1] = S.y * inv; mu[2] = S.z * inv; mu[3] = S.w * inv;
    rs[0] = rsqrtf(Q.x * inv - mu[0] * mu[0] + 1e-5f);
    rs[1] = rsqrtf(Q.y * inv - mu[1] * mu[1] + 1e-5f);
    rs[2] = rsqrtf(Q.z * inv - mu[2] * mu[2] + 1e-5f);
    rs[3] = rsqrtf(Q.w * inv - mu[3] * mu[3] + 1e-5f);

    #pragma unroll
    for (int g = 0; g < 4; ++g) {
        const float4 lw = ((const float4*)lnw_h)[g * 256 + t];
        const float4 lb = ((const float4*)lnb_h)[g * 256 + t];
        v[g].x = (v[g].x - mu[g]) * rs[g] * lw.x + lb.x;
        v[g].y = (v[g].y - mu[g]) * rs[g] * lw.y + lb.y;
        v[g].z = (v[g].z - mu[g]) * rs[g] * lw.z + lb.z;
        v[g].w = (v[g].w - mu[g]) * rs[g] * lw.w + lb.w;
    }

    const float4 cold = ((const float4*)c)[(size_t)b * 256 + t];
    float4 cn, og;
    cn.x = fsig(v[1].x + 1.0f) * cold.x + fsig(v[0].x) * ftanh(v[3].x);
    cn.y = fsig(v[1].y + 1.0f) * cold.y + fsig(v[0].y) * ftanh(v[3].y);
    cn.z = fsig(v[1].z + 1.0f) * cold.z + fsig(v[0].z) * ftanh(v[3].z);
    cn.w = fsig(v[1].w + 1.0f) * cold.w + fsig(v[0].w) * ftanh(v[3].w);
    og.x = fsig(v[2].x); og.y = fsig(v[2].y); og.z = fsig(v[2].z); og.w = fsig(v[2].w);

    float s2 = (cn.x + cn.y) + (cn.z + cn.w);
    float q2 = (cn.x * cn.x + cn.y * cn.y) + (cn.z * cn.z + cn.w * cn.w);
    #pragma unroll
    for (int o = 16; o > 0; o >>= 1) {
        s2 += __shfl_down_sync(0xffffffffu, s2, o);
        q2 += __shfl_down_sync(0xffffffffu, q2, o);
    }
    if (l == 0) red2[w] = make_float2(s2, q2);
    __syncthreads();
    if (w == 0) {
        float2 p = (l < 8) ? red2[l] : make_float2(0, 0);
        #pragma unroll
        for (int o = 4; o > 0; o >>= 1) {
            p.x += __shfl_down_sync(0xffffffffu, p.x, o);
            p.y += __shfl_down_sync(0xffffffffu, p.y, o);
        }
        if (l == 0) red2[0] = p;
    }
    __syncthreads();
    const float mu2 = red2[0].x * inv;
    const float rs2 = rsqrtf(red2[0].y * inv - mu2 * mu2 + 1e-5f);

    const float4 lwc = ((const float4*)lnw_c)[t];
    const float4 lbc = ((const float4*)lnb_c)[t];
    float4 ho;
    ho.x = og.x * ftanh((cn.x - mu2) * rs2 * lwc.x + lbc.x);
    ho.y = og.y * ftanh((cn.y - mu2) * rs2 * lwc.y + lbc.y);
    ho.z = og.z * ftanh((cn.z - mu2) * rs2 * lwc.z + lbc.z);
    ho.w = og.w * ftanh((cn.w - mu2) * rs2 * lwc.w + lbc.w);

    ((float4*)c_out)[(size_t)b * 256 + t] = cn;
    ((float4*)h_out)[(size_t)b * 256 + t] = ho;
}

// ---------------- launch ----------------
extern "C" void kernel_launch(void* const* d_in, const int* in_sizes, int n_in,
                              void* d_out, int out_size)
{
    const float* x     = (const float*)d_in[0];
    const float* h     = (const float*)d_in[1];
    const float* c     = (const float*)d_in[2];
    const float* wih   = (const float*)d_in[3];
    const float* whh   = (const float*)d_in[4];
    const float* lnw_h = (const float*)d_in[5];
    const float* lnb_h = (const float*)d_in[6];
    const float* lnw_c = (const float*)d_in[7];
    const float* lnb_c = (const float*)d_in[8];

    float* h_out = (float*)d_out;
    float* c_out = h_out + (size_t)BATCH * HIDDEN;

    cudaFuncSetAttribute(lnlstm_mma_gemm,
                         cudaFuncAttributeMaxDynamicSharedMemorySize, SMEM_B);

    lnlstm_convert<<<dim3((BATCH * KTOT / 4) / 256, 2), 256>>>(x, h, wih, whh);
    lnlstm_mma_gemm<<<dim3(NOUT / BN, BATCH / BM), 256, SMEM_B>>>();
    lnlstm_epilogue<<<BATCH, 256>>>(c, lnw_h, lnb_h, lnw_c, lnb_c, h_out, c_out);
}

// round 9
// speedup vs baseline: 5.3272x; 1.1261x over previous
#include <cuda_runtime.h>
#include <cuda_fp16.h>
#include <stdint.h>
#include <math.h>

#define BATCH  4096
#define HIDDEN 1024
#define INPUT  512
#define NOUT   4096
#define KTOT   1536
#define BM     128
#define BN     128
#define BK     64
#define NCH    (KTOT / BK)          // 24
#define STAGES 3
#define TILE_B (BM * BK * 2)        // 16384 B
#define STAGE_B (2 * TILE_B)        // 32768 B
#define SMEM_B  (STAGES * STAGE_B)  // 98304 B -> 2 CTAs/SM

// ---------------- device scratch ----------------
__device__ __half g_lin[(size_t)BATCH * NOUT];   // fp16 lin scratch (32 MB)
__device__ __half g_A[(size_t)BATCH * KTOT];
__device__ __half g_B[(size_t)NOUT  * KTOT];

// ---------------- helpers ----------------
__device__ __forceinline__ uint32_t smem_u32(const void* p) {
    uint32_t a;
    asm("{ .reg .u64 t; cvta.to.shared.u64 t, %1; cvt.u32.u64 %0, t; }" : "=r"(a) : "l"(p));
    return a;
}
#define CP16(dst, src) \
    asm volatile("cp.async.cg.shared.global [%0], [%1], 16;" :: "r"(dst), "l"(src) : "memory")
#define CP_COMMIT() asm volatile("cp.async.commit_group;" ::: "memory")
#define CP_WAIT(n)  asm volatile("cp.async.wait_group %0;" :: "n"(n) : "memory")

__device__ __forceinline__ void ldsm4(uint32_t* r, uint32_t addr) {
    asm volatile("ldmatrix.sync.aligned.m8n8.x4.shared.b16 {%0,%1,%2,%3}, [%4];"
                 : "=r"(r[0]), "=r"(r[1]), "=r"(r[2]), "=r"(r[3]) : "r"(addr));
}
__device__ __forceinline__ void mma16816(float* d, const uint32_t* a,
                                         uint32_t b0, uint32_t b1) {
    asm volatile("mma.sync.aligned.m16n8k16.row.col.f32.f16.f16.f32 "
                 "{%0,%1,%2,%3}, {%4,%5,%6,%7}, {%8,%9}, {%0,%1,%2,%3};"
                 : "+f"(d[0]), "+f"(d[1]), "+f"(d[2]), "+f"(d[3])
                 : "r"(a[0]), "r"(a[1]), "r"(a[2]), "r"(a[3]), "r"(b0), "r"(b1));
}
// tile-local smem address with XOR-8 swizzle (128 B rows, 16 B chunks)
__device__ __forceinline__ uint32_t saddr(uint32_t tile, int row, int c) {
    return tile + (uint32_t)(row * 128) + ((uint32_t)((c ^ (row & 7)) << 4));
}

// ---------------- fp16 conversion: A = [x|h], B = [wih|whh] ----------------
__global__ __launch_bounds__(256)
void lnlstm_convert(const float* __restrict__ x,  const float* __restrict__ h,
                    const float* __restrict__ wi, const float* __restrict__ wh)
{
    const uint32_t idx = blockIdx.x * 256u + threadIdx.x;
    const uint32_t e0  = idx * 4u;
    const int row = e0 / KTOT;
    const int col = e0 % KTOT;
    const float* s1 = blockIdx.y ? wi : x;
    const float* s2 = blockIdx.y ? wh : h;
    float4 v;
    if (col < INPUT) v = *(const float4*)(s1 + (size_t)row * INPUT  + col);
    else             v = *(const float4*)(s2 + (size_t)row * HIDDEN + (col - INPUT));
    __half* dst = blockIdx.y ? g_B : g_A;
    *(__half2*)(dst + e0)     = __floats2half2_rn(v.x, v.y);
    *(__half2*)(dst + e0 + 2) = __floats2half2_rn(v.z, v.w);
}

// ---------------- GEMM: g_lin = A * B^T (fp16 mma.sync, fp32 accum) ----------------
// CTA 128x128, 8 warps as 2(M) x 4(N), warp tile 64x32. 3 stages, 2 CTAs/SM.
__global__ void __launch_bounds__(256, 2)
lnlstm_mma_gemm()
{
    extern __shared__ char smem[];
    const uint32_t sb = smem_u32(smem);
    const int tid  = threadIdx.x;
    const int wid  = tid >> 5;
    const int lane = tid & 31;
    const int m0 = blockIdx.y * BM;
    const int n0 = blockIdx.x * BN;

    // cp.async mapping: thread -> (row, 4 consecutive 16B chunks)
    const int trow = tid >> 1;            // 0..127
    const int tc0  = (tid & 1) * 4;       // 0 or 4
    const __half* gA = g_A + (size_t)(m0 + trow) * KTOT + tc0 * 8;
    const __half* gB = g_B + (size_t)(n0 + trow) * KTOT + tc0 * 8;
    uint32_t dofs[4];
    #pragma unroll
    for (int c = 0; c < 4; ++c)
        dofs[c] = (uint32_t)(trow * 128) + ((uint32_t)(((tc0 + c) ^ (trow & 7)) << 4));

    // ldmatrix per-lane bases
    const int sub = lane >> 3, r8 = lane & 7;
    const int rA  = (wid >> 2) * 64 + (sub & 1) * 8 + r8;   // + mi*16
    const int cA  = sub >> 1;                               // + ks*2
    const int rB  = (wid & 3) * 32 + (sub >> 1) * 8 + r8;   // + ng*16
    const int cB  = sub & 1;                                // + ks*2

    float acc[4][4][4];
    #pragma unroll
    for (int i = 0; i < 4; ++i)
        #pragma unroll
        for (int j = 0; j < 4; ++j)
            #pragma unroll
            for (int q = 0; q < 4; ++q) acc[i][j][q] = 0.f;

    auto load_stage = [&](int ch, int s) {
        const uint32_t base = sb + (uint32_t)s * STAGE_B;
        const size_t ke = (size_t)ch * BK;
        #pragma unroll
        for (int c = 0; c < 4; ++c) {
            CP16(base + dofs[c],          gA + ke + c * 8);
            CP16(base + TILE_B + dofs[c], gB + ke + c * 8);
        }
    };

    load_stage(0, 0); CP_COMMIT();
    load_stage(1, 1); CP_COMMIT();

    #pragma unroll 1
    for (int ch = 0; ch < NCH; ++ch) {
        CP_WAIT(1);
        __syncthreads();
        if (ch + STAGES - 1 < NCH)
            load_stage(ch + STAGES - 1, (ch + STAGES - 1) % STAGES);
        CP_COMMIT();

        const uint32_t stb = sb + (uint32_t)(ch % STAGES) * STAGE_B;
        const uint32_t tA = stb, tB = stb + TILE_B;

        #pragma unroll
        for (int ks = 0; ks < 4; ++ks) {
            uint32_t a[4][4], b[2][4];
            #pragma unroll
            for (int mi = 0; mi < 4; ++mi)
                ldsm4(a[mi], saddr(tA, rA + mi * 16, ks * 2 + cA));
            #pragma unroll
            for (int ng = 0; ng < 2; ++ng)
                ldsm4(b[ng], saddr(tB, rB + ng * 16, ks * 2 + cB));
            #pragma unroll
            for (int mi = 0; mi < 4; ++mi) {
                #pragma unroll
                for (int ni = 0; ni < 4; ++ni) {
                    const int g = ni >> 1, o = (ni & 1) * 2;
                    mma16816(acc[mi][ni], a[mi], b[g][o], b[g][o + 1]);
                }
            }
        }
    }

    // writeback (fp16)
    const int g = lane >> 2, tq = lane & 3;
    #pragma unroll
    for (int mi = 0; mi < 4; ++mi) {
        const int row = m0 + (wid >> 2) * 64 + mi * 16 + g;
        #pragma unroll
        for (int ni = 0; ni < 4; ++ni) {
            const int col = n0 + (wid & 3) * 32 + ni * 8 + tq * 2;
            __half* p = g_lin + (size_t)row * NOUT + col;
            *(__half2*)p                      = __floats2half2_rn(acc[mi][ni][0], acc[mi][ni][1]);
            *(__half2*)(p + (size_t)8 * NOUT) = __floats2half2_rn(acc[mi][ni][2], acc[mi][ni][3]);
        }
    }
}

// ---------------- epilogue: chunked LN + gates + cell LN ----------------
__device__ __forceinline__ float fsig(float x)  { return 1.0f / (1.0f + __expf(-x)); }
__device__ __forceinline__ float ftanh(float x) { return 1.0f - 2.0f / (1.0f + __expf(2.0f * x)); }

__global__ __launch_bounds__(256, 4)
void lnlstm_epilogue(const float* __restrict__ c,
                     const float* __restrict__ lnw_h, const float* __restrict__ lnb_h,
                     const float* __restrict__ lnw_c, const float* __restrict__ lnb_c,
                     float* __restrict__ h_out, float* __restrict__ c_out)
{
    __shared__ float4 redS[8], redQ[8];
    __shared__ float2 red2[8];
    const int b = blockIdx.x, t = threadIdx.x;
    const int w = t >> 5, l = t & 31;
    const __half2* row2 = (const __half2*)(g_lin + (size_t)b * NOUT);

    float4 v[4];
    float s[4], q[4];
    #pragma unroll
    for (int g = 0; g < 4; ++g) {
        const float2 p0 = __half22float2(row2[g * 512 + t * 2]);
        const float2 p1 = __half22float2(row2[g * 512 + t * 2 + 1]);
        v[g] = make_float4(p0.x, p0.y, p1.x, p1.y);
        s[g] = (v[g].x + v[g].y) + (v[g].z + v[g].w);
        q[g] = (v[g].x * v[g].x + v[g].y * v[g].y) + (v[g].z * v[g].z + v[g].w * v[g].w);
    }
    #pragma unroll
    for (int o = 16; o > 0; o >>= 1) {
        #pragma unroll
        for (int g = 0; g < 4; ++g) {
            s[g] += __shfl_down_sync(0xffffffffu, s[g], o);
            q[g] += __shfl_down_sync(0xffffffffu, q[g], o);
        }
    }
    if (l == 0) { redS[w] = make_float4(s[0], s[1], s[2], s[3]);
                  redQ[w] = make_float4(q[0], q[1], q[2], q[3]); }
    __syncthreads();
    if (w == 0) {
        float4 S = (l < 8) ? redS[l] : make_float4(0, 0, 0, 0);
        float4 Q = (l < 8) ? redQ[l] : make_float4(0, 0, 0, 0);
        #pragma unroll
        for (int o = 4; o > 0; o >>= 1) {
            S.x += __shfl_down_sync(0xffffffffu, S.x, o); S.y += __shfl_down_sync(0xffffffffu, S.y, o);
            S.z += __shfl_down_sync(0xffffffffu, S.z, o); S.w += __shfl_down_sync(0xffffffffu, S.w, o);
            Q.x += __shfl_down_sync(0xffffffffu, Q.x, o); Q.y += __shfl_down_sync(0xffffffffu, Q.y, o);
            Q.z += __shfl_down_sync(0xffffffffu, Q.z, o); Q.w += __shfl_down_sync(0xffffffffu, Q.w, o);
        }
        if (l == 0) { redS[0] = S; redQ[0] = Q; }
    }
    __syncthreads();
    const float4 S = redS[0], Q = redQ[0];
    const float inv = 1.0f / HIDDEN;
    float mu[4], rs[4];
    mu[0] = S.x * inv; mu[1] = S.y * inv; mu[2] = S.z * inv; mu[3] = S.w * inv;
    rs[0] = rsqrtf(Q.x * inv - mu[0] * mu[0] + 1e-5f);
    rs[1] = rsqrtf(Q.y * inv - mu[1] * mu[1] + 1e-5f);
    rs[2] = rsqrtf(Q.z * inv - mu[2] * mu[2] + 1e-5f);
    rs[3] = rsqrtf(Q.w * inv - mu[3] * mu[3] + 1e-5f);

    #pragma unroll
    for (int g = 0; g < 4; ++g) {
        const float4 lw = ((const float4*)lnw_h)[g * 256 + t];
        const float4 lb = ((const float4*)lnb_h)[g * 256 + t];
        v[g].x = (v[g].x - mu[g]) * rs[g] * lw.x + lb.x;
        v[g].y = (v[g].y - mu[g]) * rs[g] * lw.y + lb.y;
        v[g].z = (v[g].z - mu[g]) * rs[g] * lw.z + lb.z;
        v[g].w = (v[g].w - mu[g]) * rs[g] * lw.w + lb.w;
    }

    const float4 cold = ((const float4*)c)[(size_t)b * 256 + t];
    float4 cn, og;
    cn.x = fsig(v[1].x + 1.0f) * cold.x + fsig(v[0].x) * ftanh(v[3].x);
    cn.y = fsig(v[1].y + 1.0f) * cold.y + fsig(v[0].y) * ftanh(v[3].y);
    cn.z = fsig(v[1].z + 1.0f) * cold.z + fsig(v[0].z) * ftanh(v[3].z);
    cn.w = fsig(v[1].w + 1.0f) * cold.w + fsig(v[0].w) * ftanh(v[3].w);
    og.x = fsig(v[2].x); og.y = fsig(v[2].y); og.z = fsig(v[2].z); og.w = fsig(v[2].w);

    float s2 = (cn.x + cn.y) + (cn.z + cn.w);
    float q2 = (cn.x * cn.x + cn.y * cn.y) + (cn.z * cn.z + cn.w * cn.w);
    #pragma unroll
    for (int o = 16; o > 0; o >>= 1) {
        s2 += __shfl_down_sync(0xffffffffu, s2, o);
        q2 += __shfl_down_sync(0xffffffffu, q2, o);
    }
    if (l == 0) red2[w] = make_float2(s2, q2);
    __syncthreads();
    if (w == 0) {
        float2 p = (l < 8) ? red2[l] : make_float2(0, 0);
        #pragma unroll
        for (int o = 4; o > 0; o >>= 1) {
            p.x += __shfl_down_sync(0xffffffffu, p.x, o);
            p.y += __shfl_down_sync(0xffffffffu, p.y, o);
        }
        if (l == 0) red2[0] = p;
    }
    __syncthreads();
    const float mu2 = red2[0].x * inv;
    const float rs2 = rsqrtf(red2[0].y * inv - mu2 * mu2 + 1e-5f);

    const float4 lwc = ((const float4*)lnw_c)[t];
    const float4 lbc = ((const float4*)lnb_c)[t];
    float4 ho;
    ho.x = og.x * ftanh((cn.x - mu2) * rs2 * lwc.x + lbc.x);
    ho.y = og.y * ftanh((cn.y - mu2) * rs2 * lwc.y + lbc.y);
    ho.z = og.z * ftanh((cn.z - mu2) * rs2 * lwc.z + lbc.z);
    ho.w = og.w * ftanh((cn.w - mu2) * rs2 * lwc.w + lbc.w);

    ((float4*)c_out)[(size_t)b * 256 + t] = cn;
    ((float4*)h_out)[(size_t)b * 256 + t] = ho;
}

// ---------------- launch ----------------
extern "C" void kernel_launch(void* const* d_in, const int* in_sizes, int n_in,
                              void* d_out, int out_size)
{
    const float* x     = (const float*)d_in[0];
    const float* h     = (const float*)d_in[1];
    const float* c     = (const float*)d_in[2];
    const float* wih   = (const float*)d_in[3];
    const float* whh   = (const float*)d_in[4];
    const float* lnw_h = (const float*)d_in[5];
    const float* lnb_h = (const float*)d_in[6];
    const float* lnw_c = (const float*)d_in[7];
    const float* lnb_c = (const float*)d_in[8];

    float* h_out = (float*)d_out;
    float* c_out = h_out + (size_t)BATCH * HIDDEN;

    cudaFuncSetAttribute(lnlstm_mma_gemm,
                         cudaFuncAttributeMaxDynamicSharedMemorySize, SMEM_B);

    lnlstm_convert<<<dim3((BATCH * KTOT / 4) / 256, 2), 256>>>(x, h, wih, whh);
    lnlstm_mma_gemm<<<dim3(NOUT / BN, BATCH / BM), 256, SMEM_B>>>();
    lnlstm_epilogue<<<BATCH, 256>>>(c, lnw_h, lnb_h, lnw_c, lnb_c, h_out, c_out);
}